// round 2
// baseline (speedup 1.0000x reference)
#include <cuda_runtime.h>
#include <cstddef>

#define NB   8
#define NN   4096
#define MAXD 256
#define TG   128              // toff bucket granularity (columns)
#define NTG  (NN / TG)        // 32 buckets
#define TOFFS (NTG + 1)       // 33 offsets per row

// ---------------- scratch (device globals; no allocation allowed) ----------------
static __device__ int   g_deg[NN];
static __device__ int   g_col[NN * MAXD];
static __device__ int   g_toff[NN * TOFFS];
static __device__ float g_w1t[64 * 128];          // W1^T : [DIN=64][DOUT=128]
static __device__ float g_w2t[128 * 64];          // W2^T : [DIN=128][DOUT=64]
static __device__ float g_h1[(size_t)NB * NN * 128];
static __device__ float g_x2[(size_t)NB * NN * 128];
static __device__ float g_h2[(size_t)NB * NN * 64];

// ---------------- cp.async helpers ----------------
__device__ __forceinline__ void cpasync16(unsigned saddr, const float* g)
{
    asm volatile("cp.async.cg.shared.global [%0], [%1], 16;\n" :: "r"(saddr), "l"(g));
}
__device__ __forceinline__ void cpasync_commit()
{
    asm volatile("cp.async.commit_group;\n");
}
template<int N>
__device__ __forceinline__ void cpasync_wait()
{
    asm volatile("cp.async.wait_group %0;\n" :: "n"(N));
}

// ---------------- adjacency build: warp per row + per-bucket offsets -------------
__global__ void __launch_bounds__(256) build_adj(const float* __restrict__ graph)
{
    const int w    = (blockIdx.x * blockDim.x + threadIdx.x) >> 5;  // row 0..4095
    const int lane = threadIdx.x & 31;
    const float* __restrict__ row = graph + (size_t)w * NN;
    int cnt = 0;
    if (lane == 0) g_toff[w * TOFFS] = 0;
    for (int base = 0; base < NN; base += 32) {
        float v = row[base + lane];
        unsigned msk = __ballot_sync(0xffffffffu, v != 0.0f);
        if (v != 0.0f) {
            int idx = cnt + __popc(msk & ((1u << lane) - 1u));
            if (idx < MAXD) g_col[w * MAXD + idx] = base + lane;
        }
        cnt += __popc(msk);
        if (((base + 32) & (TG - 1)) == 0 && lane == 0)
            g_toff[w * TOFFS + (base + 32) / TG] = cnt < MAXD ? cnt : MAXD;
    }
    if (lane == 0) g_deg[w] = cnt < MAXD ? cnt : MAXD;
}

// ---------------- one-time weight transpose ----------------
__global__ void __launch_bounds__(256) transpose_w(const float* __restrict__ W1,
                                                   const float* __restrict__ W2)
{
    int i = blockIdx.x * blockDim.x + threadIdx.x;   // 0..8191
    if (i < 128 * 64) {                              // W1: [128][64] -> [64][128]
        int c = i / 64, d = i % 64;
        g_w1t[d * 128 + c] = W1[i];
    }
    if (i < 64 * 128) {                              // W2: [64][128] -> [128][64]
        int c = i / 128, d = i % 128;
        g_w2t[d * 64 + c] = W2[i];
    }
}

// ---------------- register-blocked linear: out = x @ W^T ----------------
// CTA: 128 rows. Threads: (DOUT/4) colthreads x 16 rowgroups. Thread tile 8x4.
template<int DIN, int DOUT>
__device__ __forceinline__ void linear_dev(const float* __restrict__ x,
                                           const float* __restrict__ wt,  // [DIN][DOUT]
                                           float* __restrict__ out)
{
    extern __shared__ float sm[];
    float* xs = sm;                    // [128][DIN]
    float* ws = sm + 128 * DIN;        // [DIN][DOUT]
    constexpr int NT = (DOUT / 4) * 16;
    const int tid = threadIdx.x;
    const size_t row0 = (size_t)blockIdx.x * 128;

    {
        const float4* xg  = reinterpret_cast<const float4*>(x + row0 * DIN);
        float4*       xs4 = reinterpret_cast<float4*>(xs);
#pragma unroll
        for (int i = tid; i < 128 * DIN / 4; i += NT) xs4[i] = xg[i];
        const float4* wg  = reinterpret_cast<const float4*>(wt);
        float4*       ws4 = reinterpret_cast<float4*>(ws);
#pragma unroll
        for (int i = tid; i < DIN * DOUT / 4; i += NT) ws4[i] = wg[i];
    }
    __syncthreads();

    const int ct = tid % (DOUT / 4);
    const int rg = tid / (DOUT / 4);

    float acc[8][4];
#pragma unroll
    for (int r = 0; r < 8; r++)
#pragma unroll
        for (int i = 0; i < 4; i++) acc[r][i] = 0.f;

#pragma unroll 4
    for (int k4 = 0; k4 < DIN / 4; k4++) {
        float4 wv[4];
#pragma unroll
        for (int kk = 0; kk < 4; kk++)
            wv[kk] = reinterpret_cast<const float4*>(ws + (k4 * 4 + kk) * DOUT)[ct];
#pragma unroll
        for (int r = 0; r < 8; r++) {
            float4 xv = reinterpret_cast<const float4*>(xs + (rg * 8 + r) * DIN)[k4];
            acc[r][0] = fmaf(xv.x, wv[0].x, acc[r][0]);
            acc[r][1] = fmaf(xv.x, wv[0].y, acc[r][1]);
            acc[r][2] = fmaf(xv.x, wv[0].z, acc[r][2]);
            acc[r][3] = fmaf(xv.x, wv[0].w, acc[r][3]);
            acc[r][0] = fmaf(xv.y, wv[1].x, acc[r][0]);
            acc[r][1] = fmaf(xv.y, wv[1].y, acc[r][1]);
            acc[r][2] = fmaf(xv.y, wv[1].z, acc[r][2]);
            acc[r][3] = fmaf(xv.y, wv[1].w, acc[r][3]);
            acc[r][0] = fmaf(xv.z, wv[2].x, acc[r][0]);
            acc[r][1] = fmaf(xv.z, wv[2].y, acc[r][1]);
            acc[r][2] = fmaf(xv.z, wv[2].z, acc[r][2]);
            acc[r][3] = fmaf(xv.z, wv[2].w, acc[r][3]);
            acc[r][0] = fmaf(xv.w, wv[3].x, acc[r][0]);
            acc[r][1] = fmaf(xv.w, wv[3].y, acc[r][1]);
            acc[r][2] = fmaf(xv.w, wv[3].z, acc[r][2]);
            acc[r][3] = fmaf(xv.w, wv[3].w, acc[r][3]);
        }
    }

#pragma unroll
    for (int r = 0; r < 8; r++) {
        float4 o;
        o.x = acc[r][0]; o.y = acc[r][1]; o.z = acc[r][2]; o.w = acc[r][3];
        reinterpret_cast<float4*>(out + (row0 + rg * 8 + r) * DOUT)[ct] = o;
    }
}

__global__ void __launch_bounds__(512, 1) lin1_kernel(const float* __restrict__ x)
{
    linear_dev<64, 128>(x, g_w1t, g_h1);
}
__global__ void __launch_bounds__(256, 1) lin2_kernel()
{
    linear_dev<128, 64>(g_x2, g_w2t, g_h2);
}

// ---------------- tiled sparse GAT attention ----------------
// CTA: 128 rows of one batch (8 warps x 16 rows). Column tiles of CT nodes
// staged in smem (double-buffered cp.async). Online softmax per row.
template<int H, int CT, bool RELU>
__device__ __forceinline__ void attn_dev(const float* __restrict__ h,
                                         const float* __restrict__ bias,
                                         float* __restrict__ out)
{
    extern __shared__ float hs[];                 // 2 x CT x H floats
    constexpr int VEC   = H / 32;                 // 4 or 2
    constexpr int TILES = NN / CT;
    constexpr int F     = CT / TG;                // toff buckets per tile
    constexpr int WROWS = 16;

    const int tid  = threadIdx.x;
    const int w    = tid >> 5;
    const int lane = tid & 31;
    const int b    = blockIdx.x >> 5;             // 32 row-blocks per batch
    const int rb   = blockIdx.x & 31;
    const float* __restrict__ hb = h + (size_t)b * NN * H;
    const int nbase = rb * 128 + w * WROWS;

    float q[WROWS][VEC], acc[WROWS][VEC], m[WROWS], l[WROWS];
#pragma unroll
    for (int r = 0; r < WROWS; r++) {
        const float* qp = hb + (size_t)(nbase + r) * H + lane * VEC;
        if constexpr (VEC == 4) {
            float4 t = *reinterpret_cast<const float4*>(qp);
            q[r][0] = t.x; q[r][1] = t.y; q[r][2] = t.z; q[r][3] = t.w;
        } else {
            float2 t = *reinterpret_cast<const float2*>(qp);
            q[r][0] = t.x; q[r][1] = t.y;
        }
#pragma unroll
        for (int k = 0; k < VEC; k++) acc[r][k] = 0.f;
        m[r] = -1e30f; l[r] = 0.f;
    }

    const unsigned sbase = (unsigned)__cvta_generic_to_shared(hs);
    constexpr int TW = CT * H / 4;                // float4s per tile (4096)

    // prologue: tile 0 -> buf 0
    {
        const float* src = hb;
#pragma unroll
        for (int i = tid; i < TW; i += 256) cpasync16(sbase + i * 16u, src + i * 4);
        cpasync_commit();
    }

    for (int t = 0; t < TILES; t++) {
        if (t + 1 < TILES) {
            const float* src = hb + (size_t)(t + 1) * CT * H;
            const unsigned dst = sbase + ((t + 1) & 1) * (unsigned)(CT * H * 4);
#pragma unroll
            for (int i = tid; i < TW; i += 256) cpasync16(dst + i * 16u, src + i * 4);
            cpasync_commit();
            cpasync_wait<1>();
        } else {
            cpasync_wait<0>();
        }
        __syncthreads();

        const float* __restrict__ hbs = hs + (t & 1) * CT * H;
        const int cbase = t * CT;

#pragma unroll
        for (int r = 0; r < WROWS; r++) {
            const int n = nbase + r;
            const int j0 = g_toff[n * TOFFS + F * t];
            const int j1 = g_toff[n * TOFFS + F * t + F];
            const int* __restrict__ cp_ = g_col + n * MAXD;

            for (int j = j0; j < j1; j += 4) {
                float hv[4][VEC];
                float s[4];
#pragma unroll
                for (int i = 0; i < 4; i++) {
                    int jj = j + i;
                    int jc = jj < j1 ? jj : j1 - 1;
                    int lc = cp_[jc] - cbase;
                    const float* hp = hbs + lc * H + lane * VEC;
                    if constexpr (VEC == 4) {
                        float4 tv = *reinterpret_cast<const float4*>(hp);
                        hv[i][0] = tv.x; hv[i][1] = tv.y; hv[i][2] = tv.z; hv[i][3] = tv.w;
                    } else {
                        float2 tv = *reinterpret_cast<const float2*>(hp);
                        hv[i][0] = tv.x; hv[i][1] = tv.y;
                    }
                    float p = 0.f;
#pragma unroll
                    for (int k = 0; k < VEC; k++) p = fmaf(q[r][k], hv[i][k], p);
                    s[i] = p;
                }
#pragma unroll
                for (int o = 16; o > 0; o >>= 1) {
#pragma unroll
                    for (int i = 0; i < 4; i++)
                        s[i] += __shfl_xor_sync(0xffffffffu, s[i], o);
                }
#pragma unroll
                for (int i = 0; i < 4; i++)
                    if (j + i >= j1) s[i] = -1e30f;

                float gm = fmaxf(fmaxf(s[0], s[1]), fmaxf(s[2], s[3]));
                float m1 = fmaxf(m[r], gm);
                float sc = __expf(m[r] - m1);
                float e0 = __expf(s[0] - m1);
                float e1 = __expf(s[1] - m1);
                float e2 = __expf(s[2] - m1);
                float e3 = __expf(s[3] - m1);
                l[r] = fmaf(l[r], sc, (e0 + e1) + (e2 + e3));
#pragma unroll
                for (int k = 0; k < VEC; k++)
                    acc[r][k] = fmaf(e3, hv[3][k],
                                fmaf(e2, hv[2][k],
                                fmaf(e1, hv[1][k],
                                fmaf(e0, hv[0][k], acc[r][k] * sc))));
                m[r] = m1;
            }
        }
        __syncthreads();
    }

#pragma unroll
    for (int r = 0; r < WROWS; r++) {
        const float inv = 1.0f / l[r];
        float* op = out + ((size_t)b * NN + nbase + r) * H + lane * VEC;
        float rv[VEC];
#pragma unroll
        for (int k = 0; k < VEC; k++) {
            float v = fmaf(acc[r][k], inv, bias[lane * VEC + k]);
            if constexpr (RELU) v = fmaxf(v, 0.f);
            rv[k] = v;
        }
        if constexpr (VEC == 4) {
            float4 tv; tv.x = rv[0]; tv.y = rv[1]; tv.z = rv[2]; tv.w = rv[3];
            *reinterpret_cast<float4*>(op) = tv;
        } else {
            float2 tv; tv.x = rv[0]; tv.y = rv[1];
            *reinterpret_cast<float2*>(op) = tv;
        }
    }
}

__global__ void __launch_bounds__(256, 1) attn1_kernel(const float* __restrict__ bias)
{
    attn_dev<128, 128, true>(g_h1, bias, g_x2);
}
__global__ void __launch_bounds__(256, 1) attn2_kernel(const float* __restrict__ bias,
                                                       float* __restrict__ out)
{
    attn_dev<64, 256, false>(g_h2, bias, out);
}

// ---------------- launch ----------------
extern "C" void kernel_launch(void* const* d_in, const int* in_sizes, int n_in,
                              void* d_out, int out_size)
{
    (void)in_sizes; (void)n_in; (void)out_size;
    const float* x  = (const float*)d_in[0];
    const float* gr = (const float*)d_in[1];
    const float* W1 = (const float*)d_in[2];
    const float* b1 = (const float*)d_in[3];
    const float* W2 = (const float*)d_in[4];
    const float* b2 = (const float*)d_in[5];
    float* out = (float*)d_out;

    const int smem_l1 = (128 * 64 + 64 * 128) * 4;    // 64 KB
    const int smem_l2 = (128 * 128 + 128 * 64) * 4;   // 96 KB
    const int smem_at = 2 * 128 * 128 * 4;            // 128 KB (both attn layers)
    cudaFuncSetAttribute(lin1_kernel,  cudaFuncAttributeMaxDynamicSharedMemorySize, smem_l1);
    cudaFuncSetAttribute(lin2_kernel,  cudaFuncAttributeMaxDynamicSharedMemorySize, smem_l2);
    cudaFuncSetAttribute(attn1_kernel, cudaFuncAttributeMaxDynamicSharedMemorySize, smem_at);
    cudaFuncSetAttribute(attn2_kernel, cudaFuncAttributeMaxDynamicSharedMemorySize, smem_at);

    build_adj<<<NN / 8, 256>>>(gr);
    transpose_w<<<32, 256>>>(W1, W2);
    lin1_kernel<<<(NB * NN) / 128, 512, smem_l1>>>(x);      // h1 = x @ W1^T
    attn1_kernel<<<NB * 32, 256, smem_at>>>(b1);            // x2 = relu(GAT(h1)+b1)
    lin2_kernel<<<(NB * NN) / 128, 256, smem_l2>>>();       // h2 = x2 @ W2^T
    attn2_kernel<<<NB * 32, 256, smem_at>>>(b2, out);       // out = GAT(h2)+b2
}

// round 4
// speedup vs baseline: 2.9433x; 2.9433x over previous
#include <cuda_runtime.h>
#include <cstddef>

#define NB   8
#define NN   4096
#define MAXD 256

// ---------------- scratch (device globals; no allocation allowed) ----------------
static __device__ int   g_deg[NN];
static __device__ int   g_col[NN * MAXD];
static __device__ float g_w1t[64 * 128];          // W1^T : [DIN=64][DOUT=128]
static __device__ float g_w2t[128 * 64];          // W2^T : [DIN=128][DOUT=64]
static __device__ float g_h1[(size_t)NB * NN * 128];
static __device__ float g_x2[(size_t)NB * NN * 128];
static __device__ float g_h2[(size_t)NB * NN * 64];

// ---------------- adjacency build: warp per row, deterministic order -------------
__global__ void __launch_bounds__(256) build_adj(const float* __restrict__ graph)
{
    const int w    = (blockIdx.x * blockDim.x + threadIdx.x) >> 5;  // row 0..4095
    const int lane = threadIdx.x & 31;
    const float* __restrict__ row = graph + (size_t)w * NN;
    int cnt = 0;
    for (int base = 0; base < NN; base += 32) {
        float v = row[base + lane];
        unsigned msk = __ballot_sync(0xffffffffu, v != 0.0f);
        if (v != 0.0f) {
            int idx = cnt + __popc(msk & ((1u << lane) - 1u));
            if (idx < MAXD) g_col[w * MAXD + idx] = base + lane;
        }
        cnt += __popc(msk);
    }
    if (lane == 0) g_deg[w] = cnt < MAXD ? cnt : MAXD;
}

// ---------------- one-time weight transpose ----------------
__global__ void __launch_bounds__(256) transpose_w(const float* __restrict__ W1,
                                                   const float* __restrict__ W2)
{
    int i = blockIdx.x * blockDim.x + threadIdx.x;   // 0..8191
    if (i < 128 * 64) {                              // W1: [128][64] -> [64][128]
        int c = i / 64, d = i % 64;
        g_w1t[d * 128 + c] = W1[i];
    }
    if (i < 64 * 128) {                              // W2: [64][128] -> [128][64]
        int c = i / 128, d = i % 128;
        g_w2t[d * 64 + c] = W2[i];
    }
}

// ---------------- register-blocked linear: out = x @ W^T ----------------
// CTA: 128 rows. Threads: (DOUT/4) colthreads x 16 rowgroups. Thread tile 8x4.
template<int DIN, int DOUT>
__device__ __forceinline__ void linear_dev(const float* __restrict__ x,
                                           const float* __restrict__ wt,  // [DIN][DOUT]
                                           float* __restrict__ out)
{
    extern __shared__ float sm[];
    float* xs = sm;                    // [128][DIN]
    float* ws = sm + 128 * DIN;        // [DIN][DOUT]
    constexpr int NT = (DOUT / 4) * 16;
    const int tid = threadIdx.x;
    const size_t row0 = (size_t)blockIdx.x * 128;

    {
        const float4* xg  = reinterpret_cast<const float4*>(x + row0 * DIN);
        float4*       xs4 = reinterpret_cast<float4*>(xs);
#pragma unroll
        for (int i = tid; i < 128 * DIN / 4; i += NT) xs4[i] = xg[i];
        const float4* wg  = reinterpret_cast<const float4*>(wt);
        float4*       ws4 = reinterpret_cast<float4*>(ws);
#pragma unroll
        for (int i = tid; i < DIN * DOUT / 4; i += NT) ws4[i] = wg[i];
    }
    __syncthreads();

    const int ct = tid % (DOUT / 4);
    const int rg = tid / (DOUT / 4);

    float acc[8][4];
#pragma unroll
    for (int r = 0; r < 8; r++)
#pragma unroll
        for (int i = 0; i < 4; i++) acc[r][i] = 0.f;

#pragma unroll 4
    for (int k4 = 0; k4 < DIN / 4; k4++) {
        float4 wv[4];
#pragma unroll
        for (int kk = 0; kk < 4; kk++)
            wv[kk] = reinterpret_cast<const float4*>(ws + (k4 * 4 + kk) * DOUT)[ct];
#pragma unroll
        for (int r = 0; r < 8; r++) {
            float4 xv = reinterpret_cast<const float4*>(xs + (rg * 8 + r) * DIN)[k4];
            acc[r][0] = fmaf(xv.x, wv[0].x, acc[r][0]);
            acc[r][1] = fmaf(xv.x, wv[0].y, acc[r][1]);
            acc[r][2] = fmaf(xv.x, wv[0].z, acc[r][2]);
            acc[r][3] = fmaf(xv.x, wv[0].w, acc[r][3]);
            acc[r][0] = fmaf(xv.y, wv[1].x, acc[r][0]);
            acc[r][1] = fmaf(xv.y, wv[1].y, acc[r][1]);
            acc[r][2] = fmaf(xv.y, wv[1].z, acc[r][2]);
            acc[r][3] = fmaf(xv.y, wv[1].w, acc[r][3]);
            acc[r][0] = fmaf(xv.z, wv[2].x, acc[r][0]);
            acc[r][1] = fmaf(xv.z, wv[2].y, acc[r][1]);
            acc[r][2] = fmaf(xv.z, wv[2].z, acc[r][2]);
            acc[r][3] = fmaf(xv.z, wv[2].w, acc[r][3]);
            acc[r][0] = fmaf(xv.w, wv[3].x, acc[r][0]);
            acc[r][1] = fmaf(xv.w, wv[3].y, acc[r][1]);
            acc[r][2] = fmaf(xv.w, wv[3].z, acc[r][2]);
            acc[r][3] = fmaf(xv.w, wv[3].w, acc[r][3]);
        }
    }

#pragma unroll
    for (int r = 0; r < 8; r++) {
        float4 o;
        o.x = acc[r][0]; o.y = acc[r][1]; o.z = acc[r][2]; o.w = acc[r][3];
        reinterpret_cast<float4*>(out + (row0 + rg * 8 + r) * DOUT)[ct] = o;
    }
}

__global__ void __launch_bounds__(512, 1) lin1_kernel(const float* __restrict__ x)
{
    linear_dev<64, 128>(x, g_w1t, g_h1);
}
__global__ void __launch_bounds__(256, 1) lin2_kernel()
{
    linear_dev<128, 64>(g_x2, g_w2t, g_h2);
}

// ---------------- flat sparse GAT attention: warp per (b, n), 8-wide groups -----
template<int H, bool RELU>
__device__ __forceinline__ void attn_body(const float* __restrict__ h,
                                          const float* __restrict__ bias,
                                          float* __restrict__ out)
{
    constexpr int VEC = H / 32;                    // 4 (H=128) or 2 (H=64)
    const int w    = (blockIdx.x * blockDim.x + threadIdx.x) >> 5;
    const int lane = threadIdx.x & 31;
    const int b    = w >> 12;                      // / 4096
    const int n    = w & (NN - 1);
    const float* __restrict__ hb = h + (size_t)b * NN * H;

    float q[VEC];
    {
        const float* qp = hb + n * H + lane * VEC;
        if constexpr (VEC == 4) {
            float4 t = *reinterpret_cast<const float4*>(qp);
            q[0] = t.x; q[1] = t.y; q[2] = t.z; q[3] = t.w;
        } else {
            float2 t = *reinterpret_cast<const float2*>(qp);
            q[0] = t.x; q[1] = t.y;
        }
    }
    float bv[VEC];
#pragma unroll
    for (int k = 0; k < VEC; k++) bv[k] = bias[lane * VEC + k];

    float acc[VEC];
#pragma unroll
    for (int k = 0; k < VEC; k++) acc[k] = 0.f;
    float m = -1e30f, l = 0.f;

    const int d = g_deg[n];
    const int* __restrict__ cp_ = g_col + n * MAXD;

    for (int j0 = 0; j0 < d; j0 += 8) {
        // coalesced fetch of up to 8 column indices (lanes 0..7), broadcast later
        int myc = 0;
        {
            int jj = j0 + lane;
            int jc = jj < d ? jj : d - 1;
            if (lane < 8) myc = cp_[jc];
        }

        float hv[8][VEC];
        float s[8];
#pragma unroll
        for (int i = 0; i < 8; i++) {
            int c = __shfl_sync(0xffffffffu, myc, i);
            const float* hp = hb + (size_t)c * H + lane * VEC;
            if constexpr (VEC == 4) {
                float4 t = *reinterpret_cast<const float4*>(hp);
                hv[i][0] = t.x; hv[i][1] = t.y; hv[i][2] = t.z; hv[i][3] = t.w;
            } else {
                float2 t = *reinterpret_cast<const float2*>(hp);
                hv[i][0] = t.x; hv[i][1] = t.y;
            }
            float p = 0.f;
#pragma unroll
            for (int k = 0; k < VEC; k++) p = fmaf(q[k], hv[i][k], p);
            s[i] = p;
        }
        // 8 interleaved butterfly reductions
#pragma unroll
        for (int o = 16; o > 0; o >>= 1) {
#pragma unroll
            for (int i = 0; i < 8; i++) s[i] += __shfl_xor_sync(0xffffffffu, s[i], o);
        }
#pragma unroll
        for (int i = 0; i < 8; i++)
            if (j0 + i >= d) s[i] = -1e30f;        // tail -> exp == 0

        float gm = fmaxf(fmaxf(fmaxf(s[0], s[1]), fmaxf(s[2], s[3])),
                         fmaxf(fmaxf(s[4], s[5]), fmaxf(s[6], s[7])));
        float m1 = fmaxf(m, gm);
        float sc = __expf(m - m1);                  // first iter: exp(-huge) = 0
        float e[8];
#pragma unroll
        for (int i = 0; i < 8; i++) e[i] = __expf(s[i] - m1);
        l = fmaf(l, sc, ((e[0] + e[1]) + (e[2] + e[3])) + ((e[4] + e[5]) + (e[6] + e[7])));
#pragma unroll
        for (int k = 0; k < VEC; k++) {
            float a = acc[k] * sc;
#pragma unroll
            for (int i = 0; i < 8; i++) a = fmaf(e[i], hv[i][k], a);
            acc[k] = a;
        }
        m = m1;
    }

    const float inv = 1.0f / l;                     // deg >= 1 (self loop) -> l > 0
    float* op = out + ((size_t)(b * NN + n)) * H + lane * VEC;
    float r[VEC];
#pragma unroll
    for (int k = 0; k < VEC; k++) {
        float v = fmaf(acc[k], inv, bv[k]);
        if constexpr (RELU) v = fmaxf(v, 0.f);
        r[k] = v;
    }
    if constexpr (VEC == 4) {
        float4 t; t.x = r[0]; t.y = r[1]; t.z = r[2]; t.w = r[3];
        *reinterpret_cast<float4*>(op) = t;
    } else {
        float2 t; t.x = r[0]; t.y = r[1];
        *reinterpret_cast<float2*>(op) = t;
    }
}

__global__ void __launch_bounds__(256) attn1_kernel(const float* __restrict__ bias)
{
    attn_body<128, true>(g_h1, bias, g_x2);
}

__global__ void __launch_bounds__(256) attn2_kernel(const float* __restrict__ bias,
                                                    float* __restrict__ out)
{
    attn_body<64, false>(g_h2, bias, out);
}

// ---------------- launch ----------------
extern "C" void kernel_launch(void* const* d_in, const int* in_sizes, int n_in,
                              void* d_out, int out_size)
{
    (void)in_sizes; (void)n_in; (void)out_size;
    const float* x  = (const float*)d_in[0];
    const float* gr = (const float*)d_in[1];
    const float* W1 = (const float*)d_in[2];
    const float* b1 = (const float*)d_in[3];
    const float* W2 = (const float*)d_in[4];
    const float* b2 = (const float*)d_in[5];
    float* out = (float*)d_out;

    const int smem_l1 = (128 * 64 + 64 * 128) * 4;    // 64 KB
    const int smem_l2 = (128 * 128 + 128 * 64) * 4;   // 96 KB
    cudaFuncSetAttribute(lin1_kernel, cudaFuncAttributeMaxDynamicSharedMemorySize, smem_l1);
    cudaFuncSetAttribute(lin2_kernel, cudaFuncAttributeMaxDynamicSharedMemorySize, smem_l2);

    build_adj<<<NN / 8, 256>>>(gr);
    transpose_w<<<32, 256>>>(W1, W2);
    lin1_kernel<<<(NB * NN) / 128, 512, smem_l1>>>(x);    // h1 = x @ W1^T
    attn1_kernel<<<(NB * NN) / 8, 256>>>(b1);             // x2 = relu(GAT(h1)+b1)
    lin2_kernel<<<(NB * NN) / 128, 256, smem_l2>>>();     // h2 = x2 @ W2^T
    attn2_kernel<<<(NB * NN) / 8, 256>>>(b2, out);        // out = GAT(h2)+b2
}

// round 7
// speedup vs baseline: 3.3700x; 1.1450x over previous
#include <cuda_runtime.h>
#include <cstddef>

#define NB   8
#define NN   4096
#define MAXD 256
#define FULLM 0xffffffffu

typedef unsigned long long u64;

// ---------------- scratch (device globals; no allocation allowed) ----------------
static __device__ int   g_deg[NN];
static __device__ int   g_col[NN * MAXD];
static __device__ float g_w1t[64 * 128];          // W1^T : [DIN=64][DOUT=128]
static __device__ float g_w2t[128 * 64];          // W2^T : [DIN=128][DOUT=64]
static __device__ float g_h1[(size_t)NB * NN * 128];
static __device__ float g_x2[(size_t)NB * NN * 128];
static __device__ float g_h2[(size_t)NB * NN * 64];

// ---------------- f32x2 packed helpers (sm_10x) ----------------
__device__ __forceinline__ u64 pk2(float lo, float hi)
{
    u64 r; asm("mov.b64 %0, {%1,%2};" : "=l"(r) : "f"(lo), "f"(hi)); return r;
}
__device__ __forceinline__ void upk2(u64 v, float& lo, float& hi)
{
    asm("mov.b64 {%0,%1}, %2;" : "=f"(lo), "=f"(hi) : "l"(v));
}
__device__ __forceinline__ u64 fma2_(u64 a, u64 b, u64 c)
{
    u64 d; asm("fma.rn.f32x2 %0, %1, %2, %3;" : "=l"(d) : "l"(a), "l"(b), "l"(c));
    return d;
}

// ---------------- adjacency build: warp per row, deterministic order -------------
__global__ void __launch_bounds__(256) build_adj(const float* __restrict__ graph)
{
    const int w    = (blockIdx.x * blockDim.x + threadIdx.x) >> 5;  // row 0..4095
    const int lane = threadIdx.x & 31;
    const float* __restrict__ row = graph + (size_t)w * NN;
    int cnt = 0;
    for (int base = 0; base < NN; base += 32) {
        float v = row[base + lane];
        unsigned msk = __ballot_sync(FULLM, v != 0.0f);
        if (v != 0.0f) {
            int idx = cnt + __popc(msk & ((1u << lane) - 1u));
            if (idx < MAXD) g_col[w * MAXD + idx] = base + lane;
        }
        cnt += __popc(msk);
    }
    if (lane == 0) g_deg[w] = cnt < MAXD ? cnt : MAXD;
}

// ---------------- one-time weight transpose ----------------
__global__ void __launch_bounds__(256) transpose_w(const float* __restrict__ W1,
                                                   const float* __restrict__ W2)
{
    int i = blockIdx.x * blockDim.x + threadIdx.x;   // 0..8191
    if (i < 128 * 64) {                              // W1: [128][64] -> [64][128]
        int c = i / 64, d = i % 64;
        g_w1t[d * 128 + c] = W1[i];
    }
    if (i < 64 * 128) {                              // W2: [64][128] -> [128][64]
        int c = i / 128, d = i % 128;
        g_w2t[d * 64 + c] = W2[i];
    }
}

// ---------------- register-blocked linear (f32x2): out = x @ W^T ----------------
// CTA: 128 rows. Threads: (DOUT/4) colthreads x 16 rowgroups. Thread tile 8x4.
template<int DIN, int DOUT>
__device__ __forceinline__ void linear_dev(const float* __restrict__ x,
                                           const float* __restrict__ wt,  // [DIN][DOUT]
                                           float* __restrict__ out)
{
    extern __shared__ float sm[];
    float* xs = sm;                    // [128][DIN]
    float* ws = sm + 128 * DIN;        // [DIN][DOUT]
    constexpr int NT = (DOUT / 4) * 16;
    const int tid = threadIdx.x;
    const size_t row0 = (size_t)blockIdx.x * 128;

    {
        const float4* xg  = reinterpret_cast<const float4*>(x + row0 * DIN);
        float4*       xs4 = reinterpret_cast<float4*>(xs);
#pragma unroll
        for (int i = tid; i < 128 * DIN / 4; i += NT) xs4[i] = xg[i];
        const float4* wg  = reinterpret_cast<const float4*>(wt);
        float4*       ws4 = reinterpret_cast<float4*>(ws);
#pragma unroll
        for (int i = tid; i < DIN * DOUT / 4; i += NT) ws4[i] = wg[i];
    }
    __syncthreads();

    const int ct = tid % (DOUT / 4);
    const int rg = tid / (DOUT / 4);

    u64 acc01[8], acc23[8];
#pragma unroll
    for (int r = 0; r < 8; r++) { acc01[r] = 0ull; acc23[r] = 0ull; }

#pragma unroll 2
    for (int k4 = 0; k4 < DIN / 4; k4++) {
        u64 w01[4], w23[4];
#pragma unroll
        for (int kk = 0; kk < 4; kk++) {
            float4 wv = reinterpret_cast<const float4*>(ws + (k4 * 4 + kk) * DOUT)[ct];
            w01[kk] = pk2(wv.x, wv.y);
            w23[kk] = pk2(wv.z, wv.w);
        }
#pragma unroll
        for (int r = 0; r < 8; r++) {
            float4 xv = reinterpret_cast<const float4*>(xs + (rg * 8 + r) * DIN)[k4];
            u64 xx;
            xx = pk2(xv.x, xv.x);
            acc01[r] = fma2_(xx, w01[0], acc01[r]);
            acc23[r] = fma2_(xx, w23[0], acc23[r]);
            xx = pk2(xv.y, xv.y);
            acc01[r] = fma2_(xx, w01[1], acc01[r]);
            acc23[r] = fma2_(xx, w23[1], acc23[r]);
            xx = pk2(xv.z, xv.z);
            acc01[r] = fma2_(xx, w01[2], acc01[r]);
            acc23[r] = fma2_(xx, w23[2], acc23[r]);
            xx = pk2(xv.w, xv.w);
            acc01[r] = fma2_(xx, w01[3], acc01[r]);
            acc23[r] = fma2_(xx, w23[3], acc23[r]);
        }
    }

#pragma unroll
    for (int r = 0; r < 8; r++) {
        float4 o;
        upk2(acc01[r], o.x, o.y);
        upk2(acc23[r], o.z, o.w);
        reinterpret_cast<float4*>(out + (row0 + rg * 8 + r) * DOUT)[ct] = o;
    }
}

__global__ void __launch_bounds__(512, 1) lin1_kernel(const float* __restrict__ x)
{
    linear_dev<64, 128>(x, g_w1t, g_h1);
}
__global__ void __launch_bounds__(256, 1) lin2_kernel()
{
    linear_dev<128, 64>(g_x2, g_w2t, g_h2);
}

// ---------------- fold-exchange reduction helper ----------------
// Pair (x, y): returns full pair-sum; lanes with (lane & o)==0 end with x's sum,
// lanes with (lane & o)!=0 end with y's sum.
__device__ __forceinline__ float fold2(float x, float y, int o, int lane)
{
    float snd = (lane & o) ? x : y;
    snd = __shfl_xor_sync(FULLM, snd, o);
    float kp = (lane & o) ? y : x;
    return kp + snd;
}

// ---------------- flat sparse GAT attention: warp per (b, n), 8-wide groups -----
template<int H, bool RELU>
__device__ __forceinline__ void attn_body(const float* __restrict__ h,
                                          const float* __restrict__ bias,
                                          float* __restrict__ out)
{
    constexpr int VEC = H / 32;                    // 4 (H=128) or 2 (H=64)
    const int w    = (blockIdx.x * blockDim.x + threadIdx.x) >> 5;
    const int lane = threadIdx.x & 31;
    const int b    = w >> 12;                      // / 4096
    const int n    = w & (NN - 1);
    const float* __restrict__ hl = h + (size_t)b * NN * H + lane * VEC; // lane-sliced base

    float q[VEC];
    {
        const float* qp = hl + (size_t)n * H;
        if constexpr (VEC == 4) {
            float4 t = *reinterpret_cast<const float4*>(qp);
            q[0] = t.x; q[1] = t.y; q[2] = t.z; q[3] = t.w;
        } else {
            float2 t = *reinterpret_cast<const float2*>(qp);
            q[0] = t.x; q[1] = t.y;
        }
    }
    float bv[VEC];
#pragma unroll
    for (int k = 0; k < VEC; k++) bv[k] = bias[lane * VEC + k];

    float acc[VEC];
#pragma unroll
    for (int k = 0; k < VEC; k++) acc[k] = 0.f;
    float m = -1e30f, l = 0.f;

    const int d = g_deg[n];
    const int* __restrict__ cp_ = g_col + n * MAXD;

    for (int j0 = 0; j0 < d; j0 += 8) {
        // coalesced fetch of up to 8 column indices (lanes 0..7)
        int myc = 0;
        {
            int jj = j0 + lane;
            int jc = jj < d ? jj : d - 1;
            if (lane < 8) myc = cp_[jc];
        }

        float hv[8][VEC];
        float s[8];
#pragma unroll
        for (int i = 0; i < 8; i++) {
            int c = __shfl_sync(FULLM, myc, i);
            const float* hp = hl + (size_t)c * H;
            if constexpr (VEC == 4) {
                float4 t = *reinterpret_cast<const float4*>(hp);
                hv[i][0] = t.x; hv[i][1] = t.y; hv[i][2] = t.z; hv[i][3] = t.w;
            } else {
                float2 t = *reinterpret_cast<const float2*>(hp);
                hv[i][0] = t.x; hv[i][1] = t.y;
            }
            float p = 0.f;
#pragma unroll
            for (int k = 0; k < VEC; k++) p = fmaf(q[k], hv[i][k], p);
            s[i] = p;
        }

        // fold 8 partial dots over 32 lanes: 9 shuffles total.
        // Result r at lane l = full sum of value j, j bits (0,1,2) = lane bits (2,3,4).
        float a0 = fold2(s[0], s[4], 16, lane);
        float a1 = fold2(s[1], s[5], 16, lane);
        float a2 = fold2(s[2], s[6], 16, lane);
        float a3 = fold2(s[3], s[7], 16, lane);
        float b0 = fold2(a0, a2, 8, lane);
        float b1 = fold2(a1, a3, 8, lane);
        float r  = fold2(b0, b1, 4, lane);
        r += __shfl_xor_sync(FULLM, r, 2);
        r += __shfl_xor_sync(FULLM, r, 1);

        // broadcast the 8 finished sums (value j lives on lane 4*j)
        float sj[8];
#pragma unroll
        for (int i = 0; i < 8; i++) sj[i] = __shfl_sync(FULLM, r, 4 * i);
#pragma unroll
        for (int i = 0; i < 8; i++)
            if (j0 + i >= d) sj[i] = -1e30f;       // tail -> exp == 0

        // local (per-lane, warp-uniform) softmax update
        float gm = fmaxf(fmaxf(fmaxf(sj[0], sj[1]), fmaxf(sj[2], sj[3])),
                         fmaxf(fmaxf(sj[4], sj[5]), fmaxf(sj[6], sj[7])));
        if (gm > m) {                               // warp-uniform branch
            float sc = __expf(m - gm);              // first iter: exp(-huge) = 0
            l *= sc;
#pragma unroll
            for (int k = 0; k < VEC; k++) acc[k] *= sc;
            m = gm;
        }
        float e[8];
#pragma unroll
        for (int i = 0; i < 8; i++) e[i] = __expf(sj[i] - m);
        l += ((e[0] + e[1]) + (e[2] + e[3])) + ((e[4] + e[5]) + (e[6] + e[7]));
#pragma unroll
        for (int k = 0; k < VEC; k++) {
            float a = acc[k];
#pragma unroll
            for (int i = 0; i < 8; i++) a = fmaf(e[i], hv[i][k], a);
            acc[k] = a;
        }
    }

    const float inv = 1.0f / l;                     // deg >= 1 (self loop) -> l > 0
    float* op = out + ((size_t)(b * NN + n)) * H + lane * VEC;
    float rv[VEC];
#pragma unroll
    for (int k = 0; k < VEC; k++) {
        float v = fmaf(acc[k], inv, bv[k]);
        if constexpr (RELU) v = fmaxf(v, 0.f);
        rv[k] = v;
    }
    if constexpr (VEC == 4) {
        float4 t; t.x = rv[0]; t.y = rv[1]; t.z = rv[2]; t.w = rv[3];
        *reinterpret_cast<float4*>(op) = t;
    } else {
        float2 t; t.x = rv[0]; t.y = rv[1];
        *reinterpret_cast<float2*>(op) = t;
    }
}

__global__ void __launch_bounds__(256) attn1_kernel(const float* __restrict__ bias)
{
    attn_body<128, true>(g_h1, bias, g_x2);
}

__global__ void __launch_bounds__(256) attn2_kernel(const float* __restrict__ bias,
                                                    float* __restrict__ out)
{
    attn_body<64, false>(g_h2, bias, out);
}

// ---------------- launch ----------------
extern "C" void kernel_launch(void* const* d_in, const int* in_sizes, int n_in,
                              void* d_out, int out_size)
{
    (void)in_sizes; (void)n_in; (void)out_size;
    const float* x  = (const float*)d_in[0];
    const float* gr = (const float*)d_in[1];
    const float* W1 = (const float*)d_in[2];
    const float* b1 = (const float*)d_in[3];
    const float* W2 = (const float*)d_in[4];
    const float* b2 = (const float*)d_in[5];
    float* out = (float*)d_out;

    const int smem_l1 = (128 * 64 + 64 * 128) * 4;    // 64 KB
    const int smem_l2 = (128 * 128 + 128 * 64) * 4;   // 96 KB
    cudaFuncSetAttribute(lin1_kernel, cudaFuncAttributeMaxDynamicSharedMemorySize, smem_l1);
    cudaFuncSetAttribute(lin2_kernel, cudaFuncAttributeMaxDynamicSharedMemorySize, smem_l2);

    build_adj<<<NN / 8, 256>>>(gr);
    transpose_w<<<32, 256>>>(W1, W2);
    lin1_kernel<<<(NB * NN) / 128, 512, smem_l1>>>(x);    // h1 = x @ W1^T
    attn1_kernel<<<(NB * NN) / 8, 256>>>(b1);             // x2 = relu(GAT(h1)+b1)
    lin2_kernel<<<(NB * NN) / 128, 256, smem_l2>>>();     // h2 = x2 @ W2^T
    attn2_kernel<<<(NB * NN) / 8, 256>>>(b2, out);        // out = GAT(h2)+b2
}

// round 8
// speedup vs baseline: 3.7546x; 1.1141x over previous
#include <cuda_runtime.h>
#include <cstddef>

#define NB   8
#define NN   4096
#define MAXD 256
#define FULLM 0xffffffffu
#define LOG2E 1.4426950408889634f

typedef unsigned long long u64;

// ---------------- scratch (device globals; no allocation allowed) ----------------
static __device__ int   g_deg[NN];
static __device__ int   g_col[NN * MAXD];
static __device__ float g_w1t[64 * 128];          // W1^T : [DIN=64][DOUT=128]
static __device__ float g_w2t[128 * 64];          // W2^T : [DIN=128][DOUT=64]
static __device__ float g_h1[(size_t)NB * NN * 128];
static __device__ float g_x2[(size_t)NB * NN * 128];
static __device__ float g_h2[(size_t)NB * NN * 64];

// ---------------- f32x2 packed helpers (sm_10x) ----------------
__device__ __forceinline__ u64 pk2(float lo, float hi)
{
    u64 r; asm("mov.b64 %0, {%1,%2};" : "=l"(r) : "f"(lo), "f"(hi)); return r;
}
__device__ __forceinline__ void upk2(u64 v, float& lo, float& hi)
{
    asm("mov.b64 {%0,%1}, %2;" : "=f"(lo), "=f"(hi) : "l"(v));
}
__device__ __forceinline__ u64 fma2_(u64 a, u64 b, u64 c)
{
    u64 d; asm("fma.rn.f32x2 %0, %1, %2, %3;" : "=l"(d) : "l"(a), "l"(b), "l"(c));
    return d;
}
__device__ __forceinline__ float ex2_(float x)
{
    float r; asm("ex2.approx.f32 %0, %1;" : "=f"(r) : "f"(x)); return r;
}

// ---------------- adjacency build: warp per row, deterministic order -------------
__global__ void __launch_bounds__(256) build_adj(const float* __restrict__ graph)
{
    const int w    = (blockIdx.x * blockDim.x + threadIdx.x) >> 5;  // row 0..4095
    const int lane = threadIdx.x & 31;
    const float* __restrict__ row = graph + (size_t)w * NN;
    int cnt = 0;
    for (int base = 0; base < NN; base += 32) {
        float v = row[base + lane];
        unsigned msk = __ballot_sync(FULLM, v != 0.0f);
        if (v != 0.0f) {
            int idx = cnt + __popc(msk & ((1u << lane) - 1u));
            if (idx < MAXD) g_col[w * MAXD + idx] = base + lane;
        }
        cnt += __popc(msk);
    }
    if (cnt > MAXD) cnt = MAXD;
    // pad next 8 slots with self index so uniform int4 group loads stay in-bounds
    if (lane < 8) {
        int idx = cnt + lane;
        if (idx < MAXD) g_col[w * MAXD + idx] = w;
    }
    if (lane == 0) g_deg[w] = cnt;
}

// ---------------- one-time weight transpose ----------------
__global__ void __launch_bounds__(256) transpose_w(const float* __restrict__ W1,
                                                   const float* __restrict__ W2)
{
    int i = blockIdx.x * blockDim.x + threadIdx.x;   // 0..8191
    if (i < 128 * 64) {                              // W1: [128][64] -> [64][128]
        int c = i / 64, d = i % 64;
        g_w1t[d * 128 + c] = W1[i];
    }
    if (i < 64 * 128) {                              // W2: [64][128] -> [128][64]
        int c = i / 128, d = i % 128;
        g_w2t[d * 64 + c] = W2[i];
    }
}

// ---------------- register-blocked linear (f32x2): out = x @ W^T ----------------
template<int DIN, int DOUT>
__device__ __forceinline__ void linear_dev(const float* __restrict__ x,
                                           const float* __restrict__ wt,  // [DIN][DOUT]
                                           float* __restrict__ out)
{
    extern __shared__ float sm[];
    float* xs = sm;                    // [128][DIN]
    float* ws = sm + 128 * DIN;        // [DIN][DOUT]
    constexpr int NT = (DOUT / 4) * 16;
    const int tid = threadIdx.x;
    const size_t row0 = (size_t)blockIdx.x * 128;

    {
        const float4* xg  = reinterpret_cast<const float4*>(x + row0 * DIN);
        float4*       xs4 = reinterpret_cast<float4*>(xs);
#pragma unroll
        for (int i = tid; i < 128 * DIN / 4; i += NT) xs4[i] = xg[i];
        const float4* wg  = reinterpret_cast<const float4*>(wt);
        float4*       ws4 = reinterpret_cast<float4*>(ws);
#pragma unroll
        for (int i = tid; i < DIN * DOUT / 4; i += NT) ws4[i] = wg[i];
    }
    __syncthreads();

    const int ct = tid % (DOUT / 4);
    const int rg = tid / (DOUT / 4);

    u64 acc01[8], acc23[8];
#pragma unroll
    for (int r = 0; r < 8; r++) { acc01[r] = 0ull; acc23[r] = 0ull; }

#pragma unroll 2
    for (int k4 = 0; k4 < DIN / 4; k4++) {
        u64 w01[4], w23[4];
#pragma unroll
        for (int kk = 0; kk < 4; kk++) {
            float4 wv = reinterpret_cast<const float4*>(ws + (k4 * 4 + kk) * DOUT)[ct];
            w01[kk] = pk2(wv.x, wv.y);
            w23[kk] = pk2(wv.z, wv.w);
        }
#pragma unroll
        for (int r = 0; r < 8; r++) {
            float4 xv = reinterpret_cast<const float4*>(xs + (rg * 8 + r) * DIN)[k4];
            u64 xx;
            xx = pk2(xv.x, xv.x);
            acc01[r] = fma2_(xx, w01[0], acc01[r]);
            acc23[r] = fma2_(xx, w23[0], acc23[r]);
            xx = pk2(xv.y, xv.y);
            acc01[r] = fma2_(xx, w01[1], acc01[r]);
            acc23[r] = fma2_(xx, w23[1], acc23[r]);
            xx = pk2(xv.z, xv.z);
            acc01[r] = fma2_(xx, w01[2], acc01[r]);
            acc23[r] = fma2_(xx, w23[2], acc23[r]);
            xx = pk2(xv.w, xv.w);
            acc01[r] = fma2_(xx, w01[3], acc01[r]);
            acc23[r] = fma2_(xx, w23[3], acc23[r]);
        }
    }

#pragma unroll
    for (int r = 0; r < 8; r++) {
        float4 o;
        upk2(acc01[r], o.x, o.y);
        upk2(acc23[r], o.z, o.w);
        reinterpret_cast<float4*>(out + (row0 + rg * 8 + r) * DOUT)[ct] = o;
    }
}

__global__ void __launch_bounds__(512, 1) lin1_kernel(const float* __restrict__ x)
{
    linear_dev<64, 128>(x, g_w1t, g_h1);
}
__global__ void __launch_bounds__(256, 1) lin2_kernel()
{
    linear_dev<128, 64>(g_x2, g_w2t, g_h2);
}

// ---------------- fold-exchange reduction helper ----------------
__device__ __forceinline__ float fold2(float x, float y, int o, int lane)
{
    float snd = (lane & o) ? x : y;
    snd = __shfl_xor_sync(FULLM, snd, o);
    float kp = (lane & o) ? y : x;
    return kp + snd;
}

// ---------------- one 8-neighbor group (log2-domain online softmax) -------------
template<int VEC, bool TAIL>
__device__ __forceinline__ void attn_group(const float* __restrict__ hl,  // lane-sliced
                                           const int4* __restrict__ cp4,
                                           int j0, int d, int lane,
                                           const float* q,
                                           float* acc, float& m, float& l)
{
    // uniform (broadcast) fetch of 8 column indices — no shuffles, in-bounds by pad
    int4 ca = __ldg(cp4 + (j0 >> 2));
    int4 cb = __ldg(cp4 + (j0 >> 2) + 1);
    int cidx[8] = {ca.x, ca.y, ca.z, ca.w, cb.x, cb.y, cb.z, cb.w};

    float hv[8][VEC];
    float s[8];
#pragma unroll
    for (int i = 0; i < 8; i++) {
        const float* hp = hl + (size_t)cidx[i] * (VEC * 32);
        if constexpr (VEC == 4) {
            float4 t = *reinterpret_cast<const float4*>(hp);
            hv[i][0] = t.x; hv[i][1] = t.y; hv[i][2] = t.z; hv[i][3] = t.w;
        } else {
            float2 t = *reinterpret_cast<const float2*>(hp);
            hv[i][0] = t.x; hv[i][1] = t.y;
        }
        float p = 0.f;
#pragma unroll
        for (int k = 0; k < VEC; k++) p = fmaf(q[k], hv[i][k], p);
        s[i] = p;
    }

    // fold 8 partial dots over 32 lanes: 9 shuffles
    float a0 = fold2(s[0], s[4], 16, lane);
    float a1 = fold2(s[1], s[5], 16, lane);
    float a2 = fold2(s[2], s[6], 16, lane);
    float a3 = fold2(s[3], s[7], 16, lane);
    float b0 = fold2(a0, a2, 8, lane);
    float b1 = fold2(a1, a3, 8, lane);
    float r  = fold2(b0, b1, 4, lane);
    r += __shfl_xor_sync(FULLM, r, 2);
    r += __shfl_xor_sync(FULLM, r, 1);

    float sj[8];
#pragma unroll
    for (int i = 0; i < 8; i++) sj[i] = __shfl_sync(FULLM, r, 4 * i);
    if constexpr (TAIL) {
#pragma unroll
        for (int i = 0; i < 8; i++)
            if (j0 + i >= d) sj[i] = -1e30f;       // tail -> weight 0
    }

    float gm = fmaxf(fmaxf(fmaxf(sj[0], sj[1]), fmaxf(sj[2], sj[3])),
                     fmaxf(fmaxf(sj[4], sj[5]), fmaxf(sj[6], sj[7])));
    if (gm > m) {                                   // warp-uniform branch
        float sc = ex2_(m - gm);                    // first iter: ex2(-huge) = 0
        l *= sc;
#pragma unroll
        for (int k = 0; k < VEC; k++) acc[k] *= sc;
        m = gm;
    }
    float e[8];
#pragma unroll
    for (int i = 0; i < 8; i++) e[i] = ex2_(sj[i] - m);
    l += ((e[0] + e[1]) + (e[2] + e[3])) + ((e[4] + e[5]) + (e[6] + e[7]));
#pragma unroll
    for (int k = 0; k < VEC; k++) {
        float a = acc[k];
#pragma unroll
        for (int i = 0; i < 8; i++) a = fmaf(e[i], hv[i][k], a);
        acc[k] = a;
    }
}

// ---------------- flat sparse GAT attention: warp per (b, n) --------------------
template<int H, bool RELU>
__device__ __forceinline__ void attn_body(const float* __restrict__ h,
                                          const float* __restrict__ bias,
                                          float* __restrict__ out)
{
    constexpr int VEC = H / 32;                    // 4 (H=128) or 2 (H=64)
    const int w    = (blockIdx.x * blockDim.x + threadIdx.x) >> 5;
    const int lane = threadIdx.x & 31;
    const int b    = w >> 12;                      // / 4096
    const int n    = w & (NN - 1);
    const float* __restrict__ hl = h + (size_t)b * NN * H + lane * VEC;

    float q[VEC];
    {
        const float* qp = hl + (size_t)n * H;
        if constexpr (VEC == 4) {
            float4 t = *reinterpret_cast<const float4*>(qp);
            q[0] = t.x; q[1] = t.y; q[2] = t.z; q[3] = t.w;
        } else {
            float2 t = *reinterpret_cast<const float2*>(qp);
            q[0] = t.x; q[1] = t.y;
        }
        // log2-domain softmax: scale scores by log2(e) once, use ex2 later.
#pragma unroll
        for (int k = 0; k < VEC; k++) q[k] *= LOG2E;
    }
    float bv[VEC];
#pragma unroll
    for (int k = 0; k < VEC; k++) bv[k] = bias[lane * VEC + k];

    float acc[VEC];
#pragma unroll
    for (int k = 0; k < VEC; k++) acc[k] = 0.f;
    float m = -1e30f, l = 0.f;

    const int d = g_deg[n];
    const int4* __restrict__ cp4 = reinterpret_cast<const int4*>(g_col + n * MAXD);
    const int d_full = d & ~7;

    for (int j0 = 0; j0 < d_full; j0 += 8)
        attn_group<VEC, false>(hl, cp4, j0, d, lane, q, acc, m, l);
    if (d_full < d)
        attn_group<VEC, true>(hl, cp4, d_full, d, lane, q, acc, m, l);

    const float inv = 1.0f / l;                     // deg >= 1 (self loop) -> l > 0
    float* op = out + ((size_t)(b * NN + n)) * H + lane * VEC;
    float rv[VEC];
#pragma unroll
    for (int k = 0; k < VEC; k++) {
        float v = fmaf(acc[k], inv, bv[k]);
        if constexpr (RELU) v = fmaxf(v, 0.f);
        rv[k] = v;
    }
    if constexpr (VEC == 4) {
        float4 t; t.x = rv[0]; t.y = rv[1]; t.z = rv[2]; t.w = rv[3];
        *reinterpret_cast<float4*>(op) = t;
    } else {
        float2 t; t.x = rv[0]; t.y = rv[1];
        *reinterpret_cast<float2*>(op) = t;
    }
}

__global__ void __launch_bounds__(256) attn1_kernel(const float* __restrict__ bias)
{
    attn_body<128, true>(g_h1, bias, g_x2);
}

__global__ void __launch_bounds__(256) attn2_kernel(const float* __restrict__ bias,
                                                    float* __restrict__ out)
{
    attn_body<64, false>(g_h2, bias, out);
}

// ---------------- launch ----------------
extern "C" void kernel_launch(void* const* d_in, const int* in_sizes, int n_in,
                              void* d_out, int out_size)
{
    (void)in_sizes; (void)n_in; (void)out_size;
    const float* x  = (const float*)d_in[0];
    const float* gr = (const float*)d_in[1];
    const float* W1 = (const float*)d_in[2];
    const float* b1 = (const float*)d_in[3];
    const float* W2 = (const float*)d_in[4];
    const float* b2 = (const float*)d_in[5];
    float* out = (float*)d_out;

    const int smem_l1 = (128 * 64 + 64 * 128) * 4;    // 64 KB
    const int smem_l2 = (128 * 128 + 128 * 64) * 4;   // 96 KB
    cudaFuncSetAttribute(lin1_kernel, cudaFuncAttributeMaxDynamicSharedMemorySize, smem_l1);
    cudaFuncSetAttribute(lin2_kernel, cudaFuncAttributeMaxDynamicSharedMemorySize, smem_l2);

    build_adj<<<NN / 8, 256>>>(gr);
    transpose_w<<<32, 256>>>(W1, W2);
    lin1_kernel<<<(NB * NN) / 128, 512, smem_l1>>>(x);    // h1 = x @ W1^T
    attn1_kernel<<<(NB * NN) / 8, 256>>>(b1);             // x2 = relu(GAT(h1)+b1)
    lin2_kernel<<<(NB * NN) / 128, 256, smem_l2>>>();     // h2 = x2 @ W2^T
    attn2_kernel<<<(NB * NN) / 8, 256>>>(b2, out);        // out = GAT(h2)+b2
}

// round 13
// speedup vs baseline: 3.8637x; 1.0291x over previous
#include <cuda_runtime.h>
#include <cstddef>

#define NB   8
#define NN   4096
#define MAXD 256
#define FULLM 0xffffffffu
#define LOG2E 1.4426950408889634f

typedef unsigned long long u64;

// ---------------- scratch (device globals; no allocation allowed) ----------------
static __device__ int   g_deg[NN];
static __device__ int   g_col[NN * MAXD];
static __device__ float g_w1t[64 * 128];          // W1^T : [DIN=64][DOUT=128]
static __device__ float g_w2t[128 * 64];          // W2^T : [DIN=128][DOUT=64]
static __device__ float g_h1[(size_t)NB * NN * 128];
static __device__ float g_x2[(size_t)NB * NN * 128];
static __device__ float g_h2[(size_t)NB * NN * 64];

// ---------------- f32x2 packed helpers (sm_10x) ----------------
__device__ __forceinline__ u64 pk2(float lo, float hi)
{
    u64 r; asm("mov.b64 %0, {%1,%2};" : "=l"(r) : "f"(lo), "f"(hi)); return r;
}
__device__ __forceinline__ void upk2(u64 v, float& lo, float& hi)
{
    asm("mov.b64 {%0,%1}, %2;" : "=f"(lo), "=f"(hi) : "l"(v));
}
__device__ __forceinline__ u64 fma2_(u64 a, u64 b, u64 c)
{
    u64 d; asm("fma.rn.f32x2 %0, %1, %2, %3;" : "=l"(d) : "l"(a), "l"(b), "l"(c));
    return d;
}
__device__ __forceinline__ u64 mul2_(u64 a, u64 b)
{
    u64 d; asm("mul.rn.f32x2 %0, %1, %2;" : "=l"(d) : "l"(a), "l"(b));
    return d;
}
__device__ __forceinline__ float ex2_(float x)
{
    float r; asm("ex2.approx.f32 %0, %1;" : "=f"(r) : "f"(x)); return r;
}

// ---------------- adjacency build: warp per row, deterministic order -------------
__global__ void __launch_bounds__(256) build_adj(const float* __restrict__ graph)
{
    const int w    = (blockIdx.x * blockDim.x + threadIdx.x) >> 5;  // row 0..4095
    const int lane = threadIdx.x & 31;
    const float* __restrict__ row = graph + (size_t)w * NN;
    int cnt = 0;
    for (int base = 0; base < NN; base += 32) {
        float v = row[base + lane];
        unsigned msk = __ballot_sync(FULLM, v != 0.0f);
        if (v != 0.0f) {
            int idx = cnt + __popc(msk & ((1u << lane) - 1u));
            if (idx < MAXD) g_col[w * MAXD + idx] = base + lane;
        }
        cnt += __popc(msk);
    }
    if (cnt > MAXD) cnt = MAXD;
    // pad next 8 slots with self index so uniform int4 group loads stay in-bounds
    if (lane < 8) {
        int idx = cnt + lane;
        if (idx < MAXD) g_col[w * MAXD + idx] = w;
    }
    if (lane == 0) g_deg[w] = cnt;
}

// ---------------- one-time weight transpose ----------------
__global__ void __launch_bounds__(256) transpose_w(const float* __restrict__ W1,
                                                   const float* __restrict__ W2)
{
    int i = blockIdx.x * blockDim.x + threadIdx.x;   // 0..8191
    if (i < 128 * 64) {                              // W1: [128][64] -> [64][128]
        int c = i / 64, d = i % 64;
        g_w1t[d * 128 + c] = W1[i];
    }
    if (i < 64 * 128) {                              // W2: [64][128] -> [128][64]
        int c = i / 128, d = i % 128;
        g_w2t[d * 64 + c] = W2[i];
    }
}

// ---------------- register-blocked linear (f32x2): out = x @ W^T ----------------
template<int DIN, int DOUT>
__device__ __forceinline__ void linear_dev(const float* __restrict__ x,
                                           const float* __restrict__ wt,  // [DIN][DOUT]
                                           float* __restrict__ out)
{
    extern __shared__ float sm[];
    float* xs = sm;                    // [128][DIN]
    float* ws = sm + 128 * DIN;        // [DIN][DOUT]
    constexpr int NT = (DOUT / 4) * 16;
    const int tid = threadIdx.x;
    const size_t row0 = (size_t)blockIdx.x * 128;

    {
        const float4* xg  = reinterpret_cast<const float4*>(x + row0 * DIN);
        float4*       xs4 = reinterpret_cast<float4*>(xs);
#pragma unroll
        for (int i = tid; i < 128 * DIN / 4; i += NT) xs4[i] = xg[i];
        const float4* wg  = reinterpret_cast<const float4*>(wt);
        float4*       ws4 = reinterpret_cast<float4*>(ws);
#pragma unroll
        for (int i = tid; i < DIN * DOUT / 4; i += NT) ws4[i] = wg[i];
    }
    __syncthreads();

    const int ct = tid % (DOUT / 4);
    const int rg = tid / (DOUT / 4);

    u64 acc01[8], acc23[8];
#pragma unroll
    for (int r = 0; r < 8; r++) { acc01[r] = 0ull; acc23[r] = 0ull; }

#pragma unroll 2
    for (int k4 = 0; k4 < DIN / 4; k4++) {
        u64 w01[4], w23[4];
#pragma unroll
        for (int kk = 0; kk < 4; kk++) {
            float4 wv = reinterpret_cast<const float4*>(ws + (k4 * 4 + kk) * DOUT)[ct];
            w01[kk] = pk2(wv.x, wv.y);
            w23[kk] = pk2(wv.z, wv.w);
        }
#pragma unroll
        for (int r = 0; r < 8; r++) {
            float4 xv = reinterpret_cast<const float4*>(xs + (rg * 8 + r) * DIN)[k4];
            u64 xx;
            xx = pk2(xv.x, xv.x);
            acc01[r] = fma2_(xx, w01[0], acc01[r]);
            acc23[r] = fma2_(xx, w23[0], acc23[r]);
            xx = pk2(xv.y, xv.y);
            acc01[r] = fma2_(xx, w01[1], acc01[r]);
            acc23[r] = fma2_(xx, w23[1], acc23[r]);
            xx = pk2(xv.z, xv.z);
            acc01[r] = fma2_(xx, w01[2], acc01[r]);
            acc23[r] = fma2_(xx, w23[2], acc23[r]);
            xx = pk2(xv.w, xv.w);
            acc01[r] = fma2_(xx, w01[3], acc01[r]);
            acc23[r] = fma2_(xx, w23[3], acc23[r]);
        }
    }

#pragma unroll
    for (int r = 0; r < 8; r++) {
        float4 o;
        upk2(acc01[r], o.x, o.y);
        upk2(acc23[r], o.z, o.w);
        reinterpret_cast<float4*>(out + (row0 + rg * 8 + r) * DOUT)[ct] = o;
    }
}

__global__ void __launch_bounds__(512, 1) lin1_kernel(const float* __restrict__ x)
{
    linear_dev<64, 128>(x, g_w1t, g_h1);
}
__global__ void __launch_bounds__(256, 1) lin2_kernel()
{
    linear_dev<128, 64>(g_x2, g_w2t, g_h2);
}

// ---------------- fold-exchange reduction helper ----------------
__device__ __forceinline__ float fold2(float x, float y, int o, int lane)
{
    float snd = (lane & o) ? x : y;
    snd = __shfl_xor_sync(FULLM, snd, o);
    float kp = (lane & o) ? y : x;
    return kp + snd;
}

// ---------------- one 8-neighbor group (log2 softmax, f32x2 math) ---------------
// P2 = VEC/2 packed u64 per row slice.
template<int VEC, bool TAIL>
__device__ __forceinline__ void attn_group(const float* __restrict__ hl,  // lane-sliced
                                           const int4* __restrict__ cp4,
                                           int j0, int d, int lane,
                                           const u64* q2,
                                           u64* acc2, float& m, float& l)
{
    constexpr int P2 = VEC / 2;
    // uniform (broadcast) fetch of 8 column indices — no shuffles, in-bounds by pad
    int4 ca = __ldg(cp4 + (j0 >> 2));
    int4 cb = __ldg(cp4 + (j0 >> 2) + 1);
    int cidx[8] = {ca.x, ca.y, ca.z, ca.w, cb.x, cb.y, cb.z, cb.w};

    u64 hv[8][P2];
    float s[8];
#pragma unroll
    for (int i = 0; i < 8; i++) {
        const float* hp = hl + (size_t)cidx[i] * (VEC * 32);
        u64 p;
        if constexpr (P2 == 2) {
            ulonglong2 t = *reinterpret_cast<const ulonglong2*>(hp);
            hv[i][0] = t.x; hv[i][1] = t.y;
            p = fma2_(q2[0], hv[i][0], 0ull);
            p = fma2_(q2[1], hv[i][1], p);
        } else {
            hv[i][0] = *reinterpret_cast<const u64*>(hp);
            p = fma2_(q2[0], hv[i][0], 0ull);
        }
        float lo, hi; upk2(p, lo, hi);
        s[i] = lo + hi;
    }

    // fold 8 partial dots over 32 lanes: 9 shuffles
    float a0 = fold2(s[0], s[4], 16, lane);
    float a1 = fold2(s[1], s[5], 16, lane);
    float a2 = fold2(s[2], s[6], 16, lane);
    float a3 = fold2(s[3], s[7], 16, lane);
    float b0 = fold2(a0, a2, 8, lane);
    float b1 = fold2(a1, a3, 8, lane);
    float r  = fold2(b0, b1, 4, lane);
    r += __shfl_xor_sync(FULLM, r, 2);
    r += __shfl_xor_sync(FULLM, r, 1);

    float sj[8];
#pragma unroll
    for (int i = 0; i < 8; i++) sj[i] = __shfl_sync(FULLM, r, 4 * i);
    if constexpr (TAIL) {
#pragma unroll
        for (int i = 0; i < 8; i++)
            if (j0 + i >= d) sj[i] = -1e30f;       // tail -> weight 0
    }

    float gm = fmaxf(fmaxf(fmaxf(sj[0], sj[1]), fmaxf(sj[2], sj[3])),
                     fmaxf(fmaxf(sj[4], sj[5]), fmaxf(sj[6], sj[7])));
    if (gm > m) {                                   // warp-uniform branch
        float sc = ex2_(m - gm);                    // first iter: ex2(-huge) = 0
        l *= sc;
        u64 sc2 = pk2(sc, sc);
#pragma unroll
        for (int k = 0; k < P2; k++) acc2[k] = mul2_(acc2[k], sc2);
        m = gm;
    }
    float e[8];
#pragma unroll
    for (int i = 0; i < 8; i++) e[i] = ex2_(sj[i] - m);
    l += ((e[0] + e[1]) + (e[2] + e[3])) + ((e[4] + e[5]) + (e[6] + e[7]));
#pragma unroll
    for (int i = 0; i < 8; i++) {
        u64 e2 = pk2(e[i], e[i]);
#pragma unroll
        for (int k = 0; k < P2; k++) acc2[k] = fma2_(e2, hv[i][k], acc2[k]);
    }
}

// ---------------- flat sparse GAT attention: warp per (b, n) --------------------
template<int H, bool RELU>
__device__ __forceinline__ void attn_body(const float* __restrict__ h,
                                          const float* __restrict__ bias,
                                          float* __restrict__ out)
{
    constexpr int VEC = H / 32;                    // 4 (H=128) or 2 (H=64)
    constexpr int P2  = VEC / 2;
    const int w    = (blockIdx.x * blockDim.x + threadIdx.x) >> 5;
    const int lane = threadIdx.x & 31;
    const int b    = w >> 12;                      // / 4096
    const int n    = w & (NN - 1);
    const float* __restrict__ hl = h + (size_t)b * NN * H + lane * VEC;

    u64 q2[P2];
    {
        // log2-domain softmax: scale q by log2(e) once, use ex2 later.
        const u64 lg2 = pk2(LOG2E, LOG2E);
        if constexpr (P2 == 2) {
            ulonglong2 t = *reinterpret_cast<const ulonglong2*>(hl + (size_t)n * H);
            q2[0] = mul2_(t.x, lg2);
            q2[1] = mul2_(t.y, lg2);
        } else {
            u64 t = *reinterpret_cast<const u64*>(hl + (size_t)n * H);
            q2[0] = mul2_(t, lg2);
        }
    }

    u64 acc2[P2];
#pragma unroll
    for (int k = 0; k < P2; k++) acc2[k] = 0ull;
    float m = -1e30f, l = 0.f;

    const int d = g_deg[n];
    const int4* __restrict__ cp4 = reinterpret_cast<const int4*>(g_col + n * MAXD);
    const int d_full = d & ~7;

    for (int j0 = 0; j0 < d_full; j0 += 8)
        attn_group<VEC, false>(hl, cp4, j0, d, lane, q2, acc2, m, l);
    if (d_full < d)
        attn_group<VEC, true>(hl, cp4, d_full, d, lane, q2, acc2, m, l);

    const float inv = 1.0f / l;                     // deg >= 1 (self loop) -> l > 0
    float* op = out + ((size_t)(b * NN + n)) * H + lane * VEC;
    float rv[VEC];
#pragma unroll
    for (int k = 0; k < P2; k++) {
        float lo, hi; upk2(acc2[k], lo, hi);
        rv[2 * k]     = lo;
        rv[2 * k + 1] = hi;
    }
#pragma unroll
    for (int k = 0; k < VEC; k++) {
        float v = fmaf(rv[k], inv, bias[lane * VEC + k]);   // bias loaded in epilogue
        if constexpr (RELU) v = fmaxf(v, 0.f);
        rv[k] = v;
    }
    if constexpr (VEC == 4) {
        float4 t; t.x = rv[0]; t.y = rv[1]; t.z = rv[2]; t.w = rv[3];
        *reinterpret_cast<float4*>(op) = t;
    } else {
        float2 t; t.x = rv[0]; t.y = rv[1];
        *reinterpret_cast<float2*>(op) = t;
    }
}

__global__ void __launch_bounds__(256, 4) attn1_kernel(const float* __restrict__ bias)
{
    attn_body<128, true>(g_h1, bias, g_x2);
}

__global__ void __launch_bounds__(256, 4) attn2_kernel(const float* __restrict__ bias,
                                                       float* __restrict__ out)
{
    attn_body<64, false>(g_h2, bias, out);
}

// ---------------- launch ----------------
extern "C" void kernel_launch(void* const* d_in, const int* in_sizes, int n_in,
                              void* d_out, int out_size)
{
    (void)in_sizes; (void)n_in; (void)out_size;
    const float* x  = (const float*)d_in[0];
    const float* gr = (const float*)d_in[1];
    const float* W1 = (const float*)d_in[2];
    const float* b1 = (const float*)d_in[3];
    const float* W2 = (const float*)d_in[4];
    const float* b2 = (const float*)d_in[5];
    float* out = (float*)d_out;

    const int smem_l1 = (128 * 64 + 64 * 128) * 4;    // 64 KB
    const int smem_l2 = (128 * 128 + 128 * 64) * 4;   // 96 KB
    cudaFuncSetAttribute(lin1_kernel, cudaFuncAttributeMaxDynamicSharedMemorySize, smem_l1);
    cudaFuncSetAttribute(lin2_kernel, cudaFuncAttributeMaxDynamicSharedMemorySize, smem_l2);

    build_adj<<<NN / 8, 256>>>(gr);
    transpose_w<<<32, 256>>>(W1, W2);
    lin1_kernel<<<(NB * NN) / 128, 512, smem_l1>>>(x);    // h1 = x @ W1^T
    attn1_kernel<<<(NB * NN) / 8, 256>>>(b1);             // x2 = relu(GAT(h1)+b1)
    lin2_kernel<<<(NB * NN) / 128, 256, smem_l2>>>();     // h2 = x2 @ W2^T
    attn2_kernel<<<(NB * NN) / 8, 256>>>(b2, out);        // out = GAT(h2)+b2
}